// round 1
// baseline (speedup 1.0000x reference)
#include <cuda_runtime.h>
#include <math.h>

#define BB 2
#define TT 2048
#define DD 1024
#define HH 16
#define HD 64
#define MM (BB*TT)          // 4096 rows

// Scratch (device globals: no allocation allowed in kernel_launch)
__device__ float g_q[(size_t)BB*HH*TT*HD];   // (B,H,T,hd)
__device__ float g_k[(size_t)BB*HH*TT*HD];
__device__ float g_v[(size_t)BB*HH*TT*HD];
__device__ float g_att[(size_t)BB*TT*DD];    // (B,T,D)

// ---------------------------------------------------------------------------
// SGEMM: C[M=4096, N=1024] = A[4096,1024] @ W[1024,1024] + bias
// MODE 0: out row-major (B*T, D).  MODE 1: scatter to (B,H,T,hd).
// 128x128 tile, BK=8, 256 threads, 8x8 per-thread register tile.
// ---------------------------------------------------------------------------
template<int MODE>
__global__ __launch_bounds__(256, 2)
void sgemm128(const float* __restrict__ A, const float* __restrict__ W,
              const float* __restrict__ bias, float* __restrict__ out)
{
    __shared__ float As[8][128];   // transposed A tile: As[k][m]
    __shared__ float Bs[8][128];   // W tile: Bs[k][n]

    const int tid = threadIdx.x;
    const int tx = tid & 15, ty = tid >> 4;
    const int m0 = blockIdx.y * 128, n0 = blockIdx.x * 128;

    // global->shared load mapping
    const int arow = tid >> 1;            // 0..127
    const int akk  = (tid & 1) * 4;       // 0 or 4
    const int brow = tid >> 5;            // 0..7
    const int bcol = (tid & 31) * 4;      // 0..124

    const float* Ap = A + (size_t)(m0 + arow) * DD + akk;
    const float* Wp = W + (size_t)brow * DD + n0 + bcol;

    float acc[8][8];
    #pragma unroll
    for (int i = 0; i < 8; i++)
        #pragma unroll
        for (int j = 0; j < 8; j++) acc[i][j] = 0.f;

    for (int k0 = 0; k0 < DD; k0 += 8) {
        float4 a4 = *(const float4*)(Ap + k0);
        float4 b4 = *(const float4*)(Wp + (size_t)k0 * DD);
        As[akk+0][arow] = a4.x; As[akk+1][arow] = a4.y;
        As[akk+2][arow] = a4.z; As[akk+3][arow] = a4.w;
        *(float4*)&Bs[brow][bcol] = b4;
        __syncthreads();

        #pragma unroll
        for (int kk = 0; kk < 8; kk++) {
            float4 a0 = *(const float4*)&As[kk][ty*8];
            float4 a1 = *(const float4*)&As[kk][ty*8+4];
            float4 b0 = *(const float4*)&Bs[kk][tx*8];
            float4 b1 = *(const float4*)&Bs[kk][tx*8+4];
            float ar[8] = {a0.x,a0.y,a0.z,a0.w,a1.x,a1.y,a1.z,a1.w};
            float br[8] = {b0.x,b0.y,b0.z,b0.w,b1.x,b1.y,b1.z,b1.w};
            #pragma unroll
            for (int i = 0; i < 8; i++)
                #pragma unroll
                for (int j = 0; j < 8; j++)
                    acc[i][j] = fmaf(ar[i], br[j], acc[i][j]);
        }
        __syncthreads();
    }

    #pragma unroll
    for (int i = 0; i < 8; i++) {
        const int row  = m0 + ty*8 + i;
        const int col0 = n0 + tx*8;
        float* op;
        if (MODE == 0) {
            op = out + (size_t)row * DD + col0;
        } else {
            const int b = row >> 11, t = row & (TT-1);
            const int h = col0 >> 6, d = col0 & 63;
            op = out + (((size_t)(b*HH + h) * TT + t) * HD) + d;
        }
        float4 o0 = make_float4(acc[i][0]+bias[col0+0], acc[i][1]+bias[col0+1],
                                acc[i][2]+bias[col0+2], acc[i][3]+bias[col0+3]);
        float4 o1 = make_float4(acc[i][4]+bias[col0+4], acc[i][5]+bias[col0+5],
                                acc[i][6]+bias[col0+6], acc[i][7]+bias[col0+7]);
        *(float4*)op     = o0;
        *(float4*)(op+4) = o1;
    }
}

// ---------------------------------------------------------------------------
// Flash attention, causal + ALiBi(key-position) bias.
// Block: one (b,h), 64-query tile. 128 threads (16 row-groups x 8 col-groups),
// each thread owns a 4x8 fragment of S/P/O. Q,K stored transposed (d-major)
// in SMEM for float4 fragment loads; P reuses the K buffer.
// ---------------------------------------------------------------------------
#define ASTRIDE 68
#define ATT_SMEM (3*64*ASTRIDE*4)

__global__ __launch_bounds__(128, 4)
void attn64(const float* __restrict__ Q, const float* __restrict__ K,
            const float* __restrict__ V, float* __restrict__ outp)
{
    extern __shared__ float sm[];
    float (*Qt)[ASTRIDE] = (float(*)[ASTRIDE])(sm);                  // Qt[d][r]
    float (*Kt)[ASTRIDE] = (float(*)[ASTRIDE])(sm + 64*ASTRIDE);    // Kt[d][key] / P[r][c]
    float (*Vs)[ASTRIDE] = (float(*)[ASTRIDE])(sm + 2*64*ASTRIDE);  // Vs[key][d]

    const int tid = threadIdx.x;
    const int rg  = tid >> 3;      // 0..15 -> rows rg*4..rg*4+3
    const int cg  = tid & 7;       // 0..7  -> cols cg*8..cg*8+7
    const int qt  = (int)gridDim.x - 1 - (int)blockIdx.x;  // heavy tiles first
    const int bh  = blockIdx.y;
    const int b   = bh >> 4, h = bh & 15;

    const float slope = exp2f(-0.5f * (float)(h + 1));

    const float* qb  = Q + ((size_t)bh * TT + qt*64) * HD;
    const float* kb0 = K + (size_t)bh * TT * HD;
    const float* vb0 = V + (size_t)bh * TT * HD;

    // Load 64x64 Q tile transposed
    #pragma unroll
    for (int it = 0; it < 8; it++) {
        int lin = it*128 + tid;          // 0..1023
        int dg = lin & 15, r = lin >> 4;
        float4 qv = *(const float4*)(qb + r*HD + dg*4);
        Qt[dg*4+0][r] = qv.x; Qt[dg*4+1][r] = qv.y;
        Qt[dg*4+2][r] = qv.z; Qt[dg*4+3][r] = qv.w;
    }

    float acc_o[4][8];
    float m_i[4], l_i[4];
    #pragma unroll
    for (int i = 0; i < 4; i++) {
        m_i[i] = -1e30f; l_i[i] = 0.f;
        #pragma unroll
        for (int j = 0; j < 8; j++) acc_o[i][j] = 0.f;
    }

    for (int kt = 0; kt <= qt; kt++) {
        __syncthreads();  // previous iter's P/V reads done before overwrite
        const float* kb = kb0 + kt*64*HD;
        const float* vb = vb0 + kt*64*HD;
        #pragma unroll
        for (int it = 0; it < 8; it++) {
            int lin = it*128 + tid;
            int dg = lin & 15, r = lin >> 4;
            float4 kv = *(const float4*)(kb + r*HD + dg*4);
            Kt[dg*4+0][r] = kv.x; Kt[dg*4+1][r] = kv.y;
            Kt[dg*4+2][r] = kv.z; Kt[dg*4+3][r] = kv.w;
            float4 vv = *(const float4*)(vb + r*HD + dg*4);
            *(float4*)&Vs[r][dg*4] = vv;
        }
        __syncthreads();

        // S = Q K^T (4x8 fragment per thread)
        float s[4][8];
        #pragma unroll
        for (int i = 0; i < 4; i++)
            #pragma unroll
            for (int j = 0; j < 8; j++) s[i][j] = 0.f;

        #pragma unroll 4
        for (int kk = 0; kk < 64; kk++) {
            float4 qf = *(const float4*)&Qt[kk][rg*4];
            float4 k0 = *(const float4*)&Kt[kk][cg*8];
            float4 k1 = *(const float4*)&Kt[kk][cg*8+4];
            float qa[4] = {qf.x,qf.y,qf.z,qf.w};
            float ka[8] = {k0.x,k0.y,k0.z,k0.w,k1.x,k1.y,k1.z,k1.w};
            #pragma unroll
            for (int i = 0; i < 4; i++)
                #pragma unroll
                for (int j = 0; j < 8; j++)
                    s[i][j] = fmaf(qa[i], ka[j], s[i][j]);
        }

        // scale + ALiBi + causal mask, then online softmax
        const int  kcol0 = kt*64 + cg*8;
        const bool diag  = (kt == qt);
        float mtile[4];
        #pragma unroll
        for (int i = 0; i < 4; i++) {
            const int qrow = qt*64 + rg*4 + i;
            float mx = -1e30f;
            #pragma unroll
            for (int j = 0; j < 8; j++) {
                const int kidx = kcol0 + j;
                float val = fmaf(s[i][j], 0.125f, -slope * (float)(TT - 1 - kidx));
                if (diag && kidx > qrow) val = -1e30f;
                s[i][j] = val;
                mx = fmaxf(mx, val);
            }
            mx = fmaxf(mx, __shfl_xor_sync(0xffffffffu, mx, 1));
            mx = fmaxf(mx, __shfl_xor_sync(0xffffffffu, mx, 2));
            mx = fmaxf(mx, __shfl_xor_sync(0xffffffffu, mx, 4));
            mtile[i] = mx;
        }

        #pragma unroll
        for (int i = 0; i < 4; i++) {
            const float mnew = fmaxf(m_i[i], mtile[i]);
            const float corr = __expf(m_i[i] - mnew);
            m_i[i] = mnew;
            float rs = 0.f;
            #pragma unroll
            for (int j = 0; j < 8; j++) {
                const float p = __expf(s[i][j] - mnew);
                s[i][j] = p;
                rs += p;
            }
            rs += __shfl_xor_sync(0xffffffffu, rs, 1);
            rs += __shfl_xor_sync(0xffffffffu, rs, 2);
            rs += __shfl_xor_sync(0xffffffffu, rs, 4);
            l_i[i] = l_i[i]*corr + rs;
            #pragma unroll
            for (int j = 0; j < 8; j++) acc_o[i][j] *= corr;
        }

        __syncthreads();  // all threads done reading Kt before P overwrite
        #pragma unroll
        for (int i = 0; i < 4; i++) {
            *(float4*)&Kt[rg*4+i][cg*8]   = make_float4(s[i][0],s[i][1],s[i][2],s[i][3]);
            *(float4*)&Kt[rg*4+i][cg*8+4] = make_float4(s[i][4],s[i][5],s[i][6],s[i][7]);
        }
        __syncthreads();

        // O += P @ V
        #pragma unroll 4
        for (int j = 0; j < 64; j++) {
            float4 v0 = *(const float4*)&Vs[j][cg*8];
            float4 v1 = *(const float4*)&Vs[j][cg*8+4];
            float pv[4] = {Kt[rg*4+0][j], Kt[rg*4+1][j], Kt[rg*4+2][j], Kt[rg*4+3][j]};
            float va[8] = {v0.x,v0.y,v0.z,v0.w,v1.x,v1.y,v1.z,v1.w};
            #pragma unroll
            for (int i = 0; i < 4; i++)
                #pragma unroll
                for (int jj = 0; jj < 8; jj++)
                    acc_o[i][jj] = fmaf(pv[i], va[jj], acc_o[i][jj]);
        }
    }

    // normalize + write (B,T,D) with head interleave
    #pragma unroll
    for (int i = 0; i < 4; i++) {
        const float inv = 1.f / l_i[i];
        const int t = qt*64 + rg*4 + i;
        float* op = outp + (size_t)(b*TT + t) * DD + h*HD + cg*8;
        float4 o0 = make_float4(acc_o[i][0]*inv, acc_o[i][1]*inv,
                                acc_o[i][2]*inv, acc_o[i][3]*inv);
        float4 o1 = make_float4(acc_o[i][4]*inv, acc_o[i][5]*inv,
                                acc_o[i][6]*inv, acc_o[i][7]*inv);
        *(float4*)op     = o0;
        *(float4*)(op+4) = o1;
    }
}

// ---------------------------------------------------------------------------
extern "C" void kernel_launch(void* const* d_in, const int* in_sizes, int n_in,
                              void* d_out, int out_size)
{
    const float* x  = (const float*)d_in[0];
    const float* Wq = (const float*)d_in[1];
    const float* bq = (const float*)d_in[2];
    const float* Wk = (const float*)d_in[3];
    const float* bk = (const float*)d_in[4];
    const float* Wv = (const float*)d_in[5];
    const float* bv = (const float*)d_in[6];
    const float* Wo = (const float*)d_in[7];
    const float* bo = (const float*)d_in[8];
    float* out = (float*)d_out;

    float *qp, *kp, *vp, *ap;
    cudaGetSymbolAddress((void**)&qp, g_q);
    cudaGetSymbolAddress((void**)&kp, g_k);
    cudaGetSymbolAddress((void**)&vp, g_v);
    cudaGetSymbolAddress((void**)&ap, g_att);

    cudaFuncSetAttribute(attn64, cudaFuncAttributeMaxDynamicSharedMemorySize, ATT_SMEM);

    dim3 gg(DD/128, MM/128);   // (8, 32)
    sgemm128<1><<<gg, 256>>>(x, Wq, bq, qp);
    sgemm128<1><<<gg, 256>>>(x, Wk, bk, kp);
    sgemm128<1><<<gg, 256>>>(x, Wv, bv, vp);
    attn64<<<dim3(TT/64, BB*HH), 128, ATT_SMEM>>>(qp, kp, vp, ap);
    sgemm128<0><<<gg, 256>>>(ap, Wo, bo, out);
}

// round 3
// speedup vs baseline: 1.3446x; 1.3446x over previous
#include <cuda_runtime.h>
#include <cuda_bf16.h>
#include <math.h>
#include <stdint.h>

#define BB 2
#define TT 2048
#define DD 1024
#define HH 16
#define HD 64
#define MM (BB*TT)

// ---------------- scratch ----------------
__device__ float g_q[(size_t)BB*HH*TT*HD];
__device__ float g_k[(size_t)BB*HH*TT*HD];
__device__ float g_v[(size_t)BB*HH*TT*HD];
__device__ __nv_bfloat16 g_xhi[(size_t)MM*DD];
__device__ __nv_bfloat16 g_xlo[(size_t)MM*DD];
__device__ __nv_bfloat16 g_ahi[(size_t)MM*DD];
__device__ __nv_bfloat16 g_alo[(size_t)MM*DD];
__device__ __nv_bfloat16 g_whi[4*(size_t)DD*DD];
__device__ __nv_bfloat16 g_wlo[4*(size_t)DD*DD];

// ---------------- helpers ----------------
__device__ __forceinline__ float fast_exp2(float x) {
    float y; asm("ex2.approx.ftz.f32 %0, %1;" : "=f"(y) : "f"(x)); return y;
}
__device__ __forceinline__ void bsplit(float v, __nv_bfloat16& h, __nv_bfloat16& l) {
    h = __float2bfloat16(v);
    l = __float2bfloat16(v - __bfloat162float(h));
}
__device__ __forceinline__ void mma_bf16(float* c, const uint32_t* a, const uint32_t* b) {
    asm volatile("mma.sync.aligned.m16n8k16.row.col.f32.bf16.bf16.f32 "
        "{%0,%1,%2,%3}, {%4,%5,%6,%7}, {%8,%9}, {%0,%1,%2,%3};"
        : "+f"(c[0]), "+f"(c[1]), "+f"(c[2]), "+f"(c[3])
        : "r"(a[0]), "r"(a[1]), "r"(a[2]), "r"(a[3]), "r"(b[0]), "r"(b[1]));
}
// SMEM tile: 128 rows x 32 bf16 (64B/row). 16B-chunk XOR swizzle on (row>>1)&3.
__device__ __forceinline__ uint32_t lds_b32(const __nv_bfloat16* base, int row, int kbyte) {
    const int chunk = (kbyte >> 4) ^ ((row >> 1) & 3);
    const int within = kbyte & 15;
    return *(const uint32_t*)((const char*)base + row * 64 + chunk * 16 + within);
}

// ---------------------------------------------------------------------------
// split x -> bf16 hi/lo
// ---------------------------------------------------------------------------
__global__ void splitf(const float* __restrict__ in,
                       __nv_bfloat16* __restrict__ hi, __nv_bfloat16* __restrict__ lo)
{
    const int i = blockIdx.x * blockDim.x + threadIdx.x;   // float4 index
    float4 v = ((const float4*)in)[i];
    __nv_bfloat16 h0,h1,h2,h3,l0,l1,l2,l3;
    bsplit(v.x,h0,l0); bsplit(v.y,h1,l1); bsplit(v.z,h2,l2); bsplit(v.w,h3,l3);
    __nv_bfloat162* ph = (__nv_bfloat162*)hi;
    __nv_bfloat162* pl = (__nv_bfloat162*)lo;
    __nv_bfloat162 a; a.x=h0; a.y=h1; ph[2*i] = a;
    a.x=h2; a.y=h3; ph[2*i+1] = a;
    a.x=l0; a.y=l1; pl[2*i] = a;
    a.x=l2; a.y=l3; pl[2*i+1] = a;
}

// ---------------------------------------------------------------------------
// transpose + split: W[K][N] fp32 -> WT hi/lo [N][K] bf16
// ---------------------------------------------------------------------------
__global__ void transp_split(const float* __restrict__ A,
                             __nv_bfloat16* __restrict__ Bh, __nv_bfloat16* __restrict__ Bl)
{
    __shared__ float t[32][33];
    const int bx = blockIdx.x * 32, by = blockIdx.y * 32;
    const int x = threadIdx.x, y = threadIdx.y;
    #pragma unroll
    for (int i = 0; i < 32; i += 8)
        t[y + i][x] = A[(size_t)(by + y + i) * DD + bx + x];
    __syncthreads();
    #pragma unroll
    for (int i = 0; i < 32; i += 8) {
        float v = t[x][y + i];
        __nv_bfloat16 h, l; bsplit(v, h, l);
        const size_t o = (size_t)(bx + y + i) * DD + by + x;
        Bh[o] = h; Bl[o] = l;
    }
}

// ---------------------------------------------------------------------------
// bf16 split-precision GEMM via mma.sync.m16n8k16:
// C[4096,1024] = (Ahi+Alo)(Bhi+Blo)^T + bias  (drop lo*lo)
// Tile 128x128, BK=32, 8 warps (4m x 2n), warp tile 32x64.
// MODE 0: row-major out. MODE 1: scatter to (B,H,T,hd).
// ---------------------------------------------------------------------------
template<int MODE>
__global__ __launch_bounds__(256, 1)
void mma_gemm(const __nv_bfloat16* __restrict__ Ahi, const __nv_bfloat16* __restrict__ Alo,
              const __nv_bfloat16* __restrict__ Bhi, const __nv_bfloat16* __restrict__ Blo,
              const float* __restrict__ bias, float* __restrict__ out)
{
    __shared__ __align__(16) __nv_bfloat16 sAh[128*32];
    __shared__ __align__(16) __nv_bfloat16 sAl[128*32];
    __shared__ __align__(16) __nv_bfloat16 sBh[128*32];
    __shared__ __align__(16) __nv_bfloat16 sBl[128*32];

    const int tid  = threadIdx.x;
    const int wid  = tid >> 5, lane = tid & 31;
    const int g    = lane >> 2, t4 = lane & 3;
    const int wm   = wid & 3,  wn = wid >> 2;
    const int m0   = blockIdx.y * 128, n0 = blockIdx.x * 128;

    float c[2][8][4];
    #pragma unroll
    for (int mb = 0; mb < 2; mb++)
        #pragma unroll
        for (int nb = 0; nb < 8; nb++)
            #pragma unroll
            for (int j = 0; j < 4; j++) c[mb][nb][j] = 0.f;

    for (int it = 0; it < DD/32; it++) {
        const int k0 = it * 32;
        __syncthreads();
        #pragma unroll
        for (int q = 0; q < 2; q++) {
            const int cidx = q * 256 + tid;        // 512 16B-chunks per tile
            const int row = cidx >> 2, kc = cidx & 3;
            const int kcs = kc ^ ((row >> 1) & 3);
            const size_t goA = (size_t)(m0 + row) * DD + k0 + kc * 8;
            const size_t goB = (size_t)(n0 + row) * DD + k0 + kc * 8;
            *(uint4*)&sAh[row*32 + kcs*8] = *(const uint4*)(Ahi + goA);
            *(uint4*)&sAl[row*32 + kcs*8] = *(const uint4*)(Alo + goA);
            *(uint4*)&sBh[row*32 + kcs*8] = *(const uint4*)(Bhi + goB);
            *(uint4*)&sBl[row*32 + kcs*8] = *(const uint4*)(Blo + goB);
        }
        __syncthreads();

        #pragma unroll
        for (int ks = 0; ks < 2; ks++) {
            const int kb = ks * 32 + t4 * 4;
            uint32_t ah[2][4], al[2][4];
            #pragma unroll
            for (int mb = 0; mb < 2; mb++) {
                const int r0 = wm*32 + mb*16 + g;
                ah[mb][0] = lds_b32(sAh, r0,     kb);
                ah[mb][1] = lds_b32(sAh, r0 + 8, kb);
                ah[mb][2] = lds_b32(sAh, r0,     kb + 16);
                ah[mb][3] = lds_b32(sAh, r0 + 8, kb + 16);
                al[mb][0] = lds_b32(sAl, r0,     kb);
                al[mb][1] = lds_b32(sAl, r0 + 8, kb);
                al[mb][2] = lds_b32(sAl, r0,     kb + 16);
                al[mb][3] = lds_b32(sAl, r0 + 8, kb + 16);
            }
            uint32_t bh[8][2], bl[8][2];
            #pragma unroll
            for (int nb = 0; nb < 8; nb++) {
                const int rn = wn*64 + nb*8 + g;
                bh[nb][0] = lds_b32(sBh, rn, kb);
                bh[nb][1] = lds_b32(sBh, rn, kb + 16);
                bl[nb][0] = lds_b32(sBl, rn, kb);
                bl[nb][1] = lds_b32(sBl, rn, kb + 16);
            }
            #pragma unroll
            for (int mb = 0; mb < 2; mb++)
                #pragma unroll
                for (int nb = 0; nb < 8; nb++) {
                    mma_bf16(c[mb][nb], ah[mb], bh[nb]);
                    mma_bf16(c[mb][nb], ah[mb], bl[nb]);
                    mma_bf16(c[mb][nb], al[mb], bh[nb]);
                }
        }
    }

    // epilogue
    #pragma unroll
    for (int mb = 0; mb < 2; mb++) {
        const int row = m0 + wm*32 + mb*16 + g;
        #pragma unroll
        for (int nb = 0; nb < 8; nb++) {
            const int col = n0 + wn*64 + nb*8 + t4*2;
            float2 v0 = make_float2(c[mb][nb][0] + bias[col], c[mb][nb][1] + bias[col+1]);
            float2 v1 = make_float2(c[mb][nb][2] + bias[col], c[mb][nb][3] + bias[col+1]);
            if (MODE == 0) {
                *(float2*)(out + (size_t)row * DD + col)       = v0;
                *(float2*)(out + (size_t)(row + 8) * DD + col) = v1;
            } else {
                const int h = col >> 6, d = col & 63;
                const int b0 = row >> 11, t0 = row & (TT-1);
                const int b1 = (row+8) >> 11, t1 = (row+8) & (TT-1);
                *(float2*)(out + (((size_t)(b0*HH + h) * TT + t0) * HD) + d) = v0;
                *(float2*)(out + (((size_t)(b1*HH + h) * TT + t1) * HD) + d) = v1;
            }
        }
    }
}

// ---------------------------------------------------------------------------
// Flash attention, causal + ALiBi. Shuffle-based PV, exp2 softmax.
// Output written as split bf16 hi/lo (feeds final GEMM).
// ---------------------------------------------------------------------------
#define ASTRIDE 68
#define ATT_SMEM (3*64*ASTRIDE*4)

__global__ __launch_bounds__(128, 4)
void attn64(const float* __restrict__ Q, const float* __restrict__ K,
            const float* __restrict__ V,
            __nv_bfloat16* __restrict__ ohi, __nv_bfloat16* __restrict__ olo)
{
    extern __shared__ float sm[];
    float (*Qt)[ASTRIDE] = (float(*)[ASTRIDE])(sm);
    float (*Kt)[ASTRIDE] = (float(*)[ASTRIDE])(sm + 64*ASTRIDE);
    float (*Vs)[ASTRIDE] = (float(*)[ASTRIDE])(sm + 2*64*ASTRIDE);

    const int tid  = threadIdx.x;
    const int lane = tid & 31;
    const int rg   = tid >> 3;
    const int cg   = tid & 7;
    const int qt   = (int)gridDim.x - 1 - (int)blockIdx.x;
    const int bh   = blockIdx.y;
    const int b    = bh >> 4, h = bh & 15;

    const float LOG2E  = 1.4426950408889634f;
    const float scale2 = 0.125f * LOG2E;
    const float slope2 = exp2f(-0.5f * (float)(h + 1)) * LOG2E;

    const float* qb  = Q + ((size_t)bh * TT + qt*64) * HD;
    const float* kb0 = K + (size_t)bh * TT * HD;
    const float* vb0 = V + (size_t)bh * TT * HD;

    #pragma unroll
    for (int it = 0; it < 8; it++) {
        int lin = it*128 + tid;
        int dg = lin & 15, r = lin >> 4;
        float4 qv = *(const float4*)(qb + r*HD + dg*4);
        Qt[dg*4+0][r] = qv.x; Qt[dg*4+1][r] = qv.y;
        Qt[dg*4+2][r] = qv.z; Qt[dg*4+3][r] = qv.w;
    }

    float acc_o[4][8];
    float m_i[4], l_i[4];
    #pragma unroll
    for (int i = 0; i < 4; i++) {
        m_i[i] = -1e30f; l_i[i] = 0.f;
        #pragma unroll
        for (int j = 0; j < 8; j++) acc_o[i][j] = 0.f;
    }

    for (int kt = 0; kt <= qt; kt++) {
        __syncthreads();
        const float* kb = kb0 + kt*64*HD;
        const float* vb = vb0 + kt*64*HD;
        #pragma unroll
        for (int it = 0; it < 8; it++) {
            int lin = it*128 + tid;
            int dg = lin & 15, r = lin >> 4;
            float4 kv = *(const float4*)(kb + r*HD + dg*4);
            Kt[dg*4+0][r] = kv.x; Kt[dg*4+1][r] = kv.y;
            Kt[dg*4+2][r] = kv.z; Kt[dg*4+3][r] = kv.w;
            float4 vv = *(const float4*)(vb + r*HD + dg*4);
            *(float4*)&Vs[r][dg*4] = vv;
        }
        __syncthreads();

        float s[4][8];
        #pragma unroll
        for (int i = 0; i < 4; i++)
            #pragma unroll
            for (int j = 0; j < 8; j++) s[i][j] = 0.f;

        #pragma unroll 4
        for (int kk = 0; kk < 64; kk++) {
            float4 qf = *(const float4*)&Qt[kk][rg*4];
            float4 k0 = *(const float4*)&Kt[kk][cg*8];
            float4 k1 = *(const float4*)&Kt[kk][cg*8+4];
            float qa[4] = {qf.x,qf.y,qf.z,qf.w};
            float ka[8] = {k0.x,k0.y,k0.z,k0.w,k1.x,k1.y,k1.z,k1.w};
            #pragma unroll
            for (int i = 0; i < 4; i++)
                #pragma unroll
                for (int j = 0; j < 8; j++)
                    s[i][j] = fmaf(qa[i], ka[j], s[i][j]);
        }

        const int  kcol0 = kt*64 + cg*8;
        const bool diag  = (kt == qt);
        #pragma unroll
        for (int i = 0; i < 4; i++) {
            const int qrow = qt*64 + rg*4 + i;
            float mx = -1e30f;
            #pragma unroll
            for (int j = 0; j < 8; j++) {
                const int kidx = kcol0 + j;
                float val = fmaf(s[i][j], scale2, -slope2 * (float)(TT - 1 - kidx));
                if (diag && kidx > qrow) val = -1e30f;
                s[i][j] = val;
                mx = fmaxf(mx, val);
            }
            mx = fmaxf(mx, __shfl_xor_sync(0xffffffffu, mx, 1));
            mx = fmaxf(mx, __shfl_xor_sync(0xffffffffu, mx, 2));
            mx = fmaxf(mx, __shfl_xor_sync(0xffffffffu, mx, 4));
            const float mnew = fmaxf(m_i[i], mx);
            const float corr = fast_exp2(m_i[i] - mnew);
            m_i[i] = mnew;
            float rs = 0.f;
            #pragma unroll
            for (int j = 0; j < 8; j++) {
                const float p = fast_exp2(s[i][j] - mnew);
                s[i][j] = p;
                rs += p;
            }
            rs += __shfl_xor_sync(0xffffffffu, rs, 1);
            rs += __shfl_xor_sync(0xffffffffu, rs, 2);
            rs += __shfl_xor_sync(0xffffffffu, rs, 4);
            l_i[i] = l_i[i]*corr + rs;
            #pragma unroll
            for (int j = 0; j < 8; j++) acc_o[i][j] *= corr;
        }

        #pragma unroll 2
        for (int kb2 = 0; kb2 < 8; kb2++) {
            const int src = (lane & 24) + kb2;
            #pragma unroll
            for (int jl = 0; jl < 8; jl++) {
                const int kk = kb2*8 + jl;
                float4 v0 = *(const float4*)&Vs[kk][cg*8];
                float4 v1 = *(const float4*)&Vs[kk][cg*8+4];
                float p0 = __shfl_sync(0xffffffffu, s[0][jl], src);
                float p1 = __shfl_sync(0xffffffffu, s[1][jl], src);
                float p2 = __shfl_sync(0xffffffffu, s[2][jl], src);
                float p3 = __shfl_sync(0xffffffffu, s[3][jl], src);
                float va[8] = {v0.x,v0.y,v0.z,v0.w,v1.x,v1.y,v1.z,v1.w};
                #pragma unroll
                for (int jj = 0; jj < 8; jj++) {
                    acc_o[0][jj] = fmaf(p0, va[jj], acc_o[0][jj]);
                    acc_o[1][jj] = fmaf(p1, va[jj], acc_o[1][jj]);
                    acc_o[2][jj] = fmaf(p2, va[jj], acc_o[2][jj]);
                    acc_o[3][jj] = fmaf(p3, va[jj], acc_o[3][jj]);
                }
            }
        }
    }

    #pragma unroll
    for (int i = 0; i < 4; i++) {
        const float inv = 1.f / l_i[i];
        const int t = qt*64 + rg*4 + i;
        const size_t o = (size_t)(b*TT + t) * DD + h*HD + cg*8;
        #pragma unroll
        for (int j = 0; j < 8; j += 2) {
            __nv_bfloat16 h0,h1,l0,l1;
            bsplit(acc_o[i][j]*inv,   h0, l0);
            bsplit(acc_o[i][j+1]*inv, h1, l1);
            __nv_bfloat162 ph; ph.x=h0; ph.y=h1;
            __nv_bfloat162 pl; pl.x=l0; pl.y=l1;
            *(__nv_bfloat162*)(ohi + o + j) = ph;
            *(__nv_bfloat162*)(olo + o + j) = pl;
        }
    }
}

// ---------------------------------------------------------------------------
extern "C" void kernel_launch(void* const* d_in, const int* in_sizes, int n_in,
                              void* d_out, int out_size)
{
    const float* x  = (const float*)d_in[0];
    const float* Wq = (const float*)d_in[1];
    const float* bq = (const float*)d_in[2];
    const float* Wk = (const float*)d_in[3];
    const float* bk = (const float*)d_in[4];
    const float* Wv = (const float*)d_in[5];
    const float* bv = (const float*)d_in[6];
    const float* Wo = (const float*)d_in[7];
    const float* bo = (const float*)d_in[8];
    float* out = (float*)d_out;

    float *qp, *kp, *vp;
    __nv_bfloat16 *xhi, *xlo, *ahi, *alo, *whi, *wlo;
    cudaGetSymbolAddress((void**)&qp, g_q);
    cudaGetSymbolAddress((void**)&kp, g_k);
    cudaGetSymbolAddress((void**)&vp, g_v);
    cudaGetSymbolAddress((void**)&xhi, g_xhi);
    cudaGetSymbolAddress((void**)&xlo, g_xlo);
    cudaGetSymbolAddress((void**)&ahi, g_ahi);
    cudaGetSymbolAddress((void**)&alo, g_alo);
    cudaGetSymbolAddress((void**)&whi, g_whi);
    cudaGetSymbolAddress((void**)&wlo, g_wlo);

    cudaFuncSetAttribute(attn64, cudaFuncAttributeMaxDynamicSharedMemorySize, ATT_SMEM);

    const size_t WSZ = (size_t)DD * DD;

    splitf<<<(MM*DD/4)/256, 256>>>(x, xhi, xlo);
    dim3 tg(32, 32), tb(32, 8);
    transp_split<<<tg, tb>>>(Wq, whi + 0*WSZ, wlo + 0*WSZ);
    transp_split<<<tg, tb>>>(Wk, whi + 1*WSZ, wlo + 1*WSZ);
    transp_split<<<tg, tb>>>(Wv, whi + 2*WSZ, wlo + 2*WSZ);
    transp_split<<<tg, tb>>>(Wo, whi + 3*WSZ, wlo + 3*WSZ);

    dim3 gg(DD/128, MM/128);   // (8, 32)
    mma_gemm<1><<<gg, 256>>>(xhi, xlo, whi + 0*WSZ, wlo + 0*WSZ, bq, qp);
    mma_gemm<1><<<gg, 256>>>(xhi, xlo, whi + 1*WSZ, wlo + 1*WSZ, bk, kp);
    mma_gemm<1><<<gg, 256>>>(xhi, xlo, whi + 2*WSZ, wlo + 2*WSZ, bv, vp);
    attn64<<<dim3(TT/64, BB*HH), 128, ATT_SMEM>>>(qp, kp, vp, ahi, alo);
    mma_gemm<0><<<gg, 256>>>(ahi, alo, whi + 3*WSZ, wlo + 3*WSZ, bo, out);
}

// round 4
// speedup vs baseline: 3.3487x; 2.4905x over previous
#include <cuda_runtime.h>
#include <cuda_bf16.h>
#include <math.h>
#include <stdint.h>

#define BB 2
#define TT 2048
#define DD 1024
#define HH 16
#define HD 64
#define MM (BB*TT)

// ---------------- scratch ----------------
__device__ __nv_bfloat16 g_xhi[(size_t)MM*DD];
__device__ __nv_bfloat16 g_xlo[(size_t)MM*DD];
__device__ __nv_bfloat16 g_qhi[(size_t)MM*DD];
__device__ __nv_bfloat16 g_qlo[(size_t)MM*DD];
__device__ __nv_bfloat16 g_khi[(size_t)MM*DD];
__device__ __nv_bfloat16 g_klo[(size_t)MM*DD];
__device__ __nv_bfloat16 g_vhi[(size_t)MM*DD];
__device__ __nv_bfloat16 g_vlo[(size_t)MM*DD];
__device__ __nv_bfloat16 g_ahi[(size_t)MM*DD];
__device__ __nv_bfloat16 g_alo[(size_t)MM*DD];
__device__ __nv_bfloat16 g_whi[4*(size_t)DD*DD];
__device__ __nv_bfloat16 g_wlo[4*(size_t)DD*DD];

// ---------------- helpers ----------------
__device__ __forceinline__ uint32_t smem_u32(const void* p) {
    uint32_t a;
    asm("{ .reg .u64 t; cvta.to.shared.u64 t, %1; cvt.u32.u64 %0, t; }" : "=r"(a) : "l"(p));
    return a;
}
__device__ __forceinline__ float fast_exp2(float x) {
    float y; asm("ex2.approx.ftz.f32 %0, %1;" : "=f"(y) : "f"(x)); return y;
}
__device__ __forceinline__ void bsplit(float v, __nv_bfloat16& h, __nv_bfloat16& l) {
    h = __float2bfloat16(v);
    l = __float2bfloat16(v - __bfloat162float(h));
}
__device__ __forceinline__ void mma_bf16(float* c, const uint32_t* a, uint32_t b0, uint32_t b1) {
    asm volatile("mma.sync.aligned.m16n8k16.row.col.f32.bf16.bf16.f32 "
        "{%0,%1,%2,%3}, {%4,%5,%6,%7}, {%8,%9}, {%0,%1,%2,%3};"
        : "+f"(c[0]), "+f"(c[1]), "+f"(c[2]), "+f"(c[3])
        : "r"(a[0]), "r"(a[1]), "r"(a[2]), "r"(a[3]), "r"(b0), "r"(b1));
}
__device__ __forceinline__ void ldsm4(uint32_t addr, uint32_t* r) {
    asm volatile("ldmatrix.sync.aligned.m8n8.x4.shared.b16 {%0,%1,%2,%3}, [%4];"
        : "=r"(r[0]), "=r"(r[1]), "=r"(r[2]), "=r"(r[3]) : "r"(addr));
}
__device__ __forceinline__ void ldsm4t(uint32_t addr, uint32_t* r) {
    asm volatile("ldmatrix.sync.aligned.m8n8.x4.trans.shared.b16 {%0,%1,%2,%3}, [%4];"
        : "=r"(r[0]), "=r"(r[1]), "=r"(r[2]), "=r"(r[3]) : "r"(addr));
}
__device__ __forceinline__ void cpa(uint32_t dst, const void* src) {
    asm volatile("cp.async.ca.shared.global [%0], [%1], 16;" :: "r"(dst), "l"(src));
}
__device__ __forceinline__ void commitg() {
    asm volatile("cp.async.commit_group;" ::: "memory");
}
template<int N> __device__ __forceinline__ void waitg() {
    asm volatile("cp.async.wait_group %0;" :: "n"(N) : "memory");
}
// pack (x,y) into bf16x2 hi + residual lo
__device__ __forceinline__ void packsplit(float x, float y, uint32_t& hi, uint32_t& lo) {
    asm("cvt.rn.bf16x2.f32 %0, %1, %2;" : "=r"(hi) : "f"(y), "f"(x));
    __nv_bfloat162 t = *(__nv_bfloat162*)&hi;
    float rx = x - __bfloat162float(t.x);
    float ry = y - __bfloat162float(t.y);
    asm("cvt.rn.bf16x2.f32 %0, %1, %2;" : "=r"(lo) : "f"(ry), "f"(rx));
}

// ---------------------------------------------------------------------------
// split x -> bf16 hi/lo
// ---------------------------------------------------------------------------
__global__ void splitf(const float* __restrict__ in,
                       __nv_bfloat16* __restrict__ hi, __nv_bfloat16* __restrict__ lo)
{
    const int i = blockIdx.x * blockDim.x + threadIdx.x;
    float4 v = ((const float4*)in)[i];
    __nv_bfloat16 h0,h1,h2,h3,l0,l1,l2,l3;
    bsplit(v.x,h0,l0); bsplit(v.y,h1,l1); bsplit(v.z,h2,l2); bsplit(v.w,h3,l3);
    __nv_bfloat162* ph = (__nv_bfloat162*)hi;
    __nv_bfloat162* pl = (__nv_bfloat162*)lo;
    __nv_bfloat162 a; a.x=h0; a.y=h1; ph[2*i] = a;
    a.x=h2; a.y=h3; ph[2*i+1] = a;
    a.x=l0; a.y=l1; pl[2*i] = a;
    a.x=l2; a.y=l3; pl[2*i+1] = a;
}

// ---------------------------------------------------------------------------
// transpose + split: W[K][N] fp32 -> WT hi/lo [N][K] bf16
// ---------------------------------------------------------------------------
__global__ void transp_split(const float* __restrict__ A,
                             __nv_bfloat16* __restrict__ Bh, __nv_bfloat16* __restrict__ Bl)
{
    __shared__ float t[32][33];
    const int bx = blockIdx.x * 32, by = blockIdx.y * 32;
    const int x = threadIdx.x, y = threadIdx.y;
    #pragma unroll
    for (int i = 0; i < 32; i += 8)
        t[y + i][x] = A[(size_t)(by + y + i) * DD + bx + x];
    __syncthreads();
    #pragma unroll
    for (int i = 0; i < 32; i += 8) {
        float v = t[x][y + i];
        __nv_bfloat16 h, l; bsplit(v, h, l);
        const size_t o = (size_t)(bx + y + i) * DD + by + x;
        Bh[o] = h; Bl[o] = l;
    }
}

// ---------------------------------------------------------------------------
// GEMM v2: split-bf16 mma.sync + ldmatrix + cp.async double buffer.
// C[4096,1024] = (Ahi+Alo)(Bhi+Blo)^T + bias (lo*lo dropped).
// Tile 128x128, BK=32, 8 warps (4m x 2n). Tiles: 64B rows, chunk^((row>>1)&3).
// MODE 0: fp32 row-major out.  MODE 1: split bf16 hi/lo scatter to (B,H,T,hd).
// ---------------------------------------------------------------------------
#define G_AH 0
#define G_AL 8192
#define G_BH 16384
#define G_BL 24576
#define G_STG 32768
#define GEMM_SMEM 65536

#define GEMM_LOAD(IT, STG) { \
    const int k0_ = (IT) * 32; \
    _Pragma("unroll") \
    for (int q_ = 0; q_ < 8; q_++) { \
        int idx_ = q_ * 256 + tid; \
        int buf_ = idx_ >> 9, wi_ = idx_ & 511; \
        int row_ = wi_ >> 2, kc_ = wi_ & 3; \
        uint32_t dst_ = sb + (STG)*G_STG + buf_*8192 + row_*64 + ((kc_ ^ ((row_>>1)&3)) << 4); \
        const __nv_bfloat16* src_; \
        if      (buf_ == 0) src_ = Ahi + (size_t)(m0 + row_)*DD + k0_ + kc_*8; \
        else if (buf_ == 1) src_ = Alo + (size_t)(m0 + row_)*DD + k0_ + kc_*8; \
        else if (buf_ == 2) src_ = Bhi + (size_t)(n0 + row_)*DD + k0_ + kc_*8; \
        else                src_ = Blo + (size_t)(n0 + row_)*DD + k0_ + kc_*8; \
        cpa(dst_, src_); \
    } }

template<int MODE>
__global__ __launch_bounds__(256, 2)
void mma_gemm(const __nv_bfloat16* __restrict__ Ahi, const __nv_bfloat16* __restrict__ Alo,
              const __nv_bfloat16* __restrict__ Bhi, const __nv_bfloat16* __restrict__ Blo,
              const float* __restrict__ bias, float* __restrict__ outf,
              __nv_bfloat16* __restrict__ outh, __nv_bfloat16* __restrict__ outl)
{
    extern __shared__ __align__(1024) char smem[];
    const uint32_t sb = smem_u32(smem);
    const int tid  = threadIdx.x;
    const int wid  = tid >> 5, lane = tid & 31;
    const int g    = lane >> 2, t4 = lane & 3;
    const int grp  = lane >> 3, wi = lane & 7;
    const int wm   = wid & 3,  wn = wid >> 2;
    const int m0   = blockIdx.y * 128, n0 = blockIdx.x * 128;

    float c[2][8][4];
    #pragma unroll
    for (int mb = 0; mb < 2; mb++)
        #pragma unroll
        for (int nb = 0; nb < 8; nb++)
            #pragma unroll
            for (int j = 0; j < 4; j++) c[mb][nb][j] = 0.f;

    GEMM_LOAD(0, 0); commitg();

    for (int it = 0; it < DD/32; it++) {
        if (it + 1 < DD/32) { GEMM_LOAD(it+1, (it+1)&1); commitg(); waitg<1>(); }
        else { waitg<0>(); }
        __syncthreads();
        const uint32_t base = sb + (it & 1) * G_STG;

        #pragma unroll
        for (int ks = 0; ks < 2; ks++) {
            uint32_t ah[2][4], al[2][4];
            #pragma unroll
            for (int mb = 0; mb < 2; mb++) {
                const int row = wm*32 + mb*16 + (grp & 1)*8 + wi;
                const int kb  = ks*32 + (grp >> 1)*16;
                const uint32_t off = row*64 + ((((kb >> 4) ^ ((row >> 1) & 3))) << 4);
                ldsm4(base + G_AH + off, ah[mb]);
                ldsm4(base + G_AL + off, al[mb]);
            }
            #pragma unroll
            for (int nbp = 0; nbp < 4; nbp++) {
                const int rowb = wn*64 + nbp*16 + (grp >> 1)*8 + wi;
                const int kb2  = ks*32 + (grp & 1)*16;
                const uint32_t offb = rowb*64 + ((((kb2 >> 4) ^ ((rowb >> 1) & 3))) << 4);
                uint32_t bh[4], bl[4];
                ldsm4(base + G_BH + offb, bh);
                ldsm4(base + G_BL + offb, bl);
                #pragma unroll
                for (int mb = 0; mb < 2; mb++) {
                    mma_bf16(c[mb][2*nbp],   ah[mb], bh[0], bh[1]);
                    mma_bf16(c[mb][2*nbp],   al[mb], bh[0], bh[1]);
                    mma_bf16(c[mb][2*nbp],   ah[mb], bl[0], bl[1]);
                    mma_bf16(c[mb][2*nbp+1], ah[mb], bh[2], bh[3]);
                    mma_bf16(c[mb][2*nbp+1], al[mb], bh[2], bh[3]);
                    mma_bf16(c[mb][2*nbp+1], ah[mb], bl[2], bl[3]);
                }
            }
        }
        __syncthreads();
    }

    // epilogue
    #pragma unroll
    for (int mb = 0; mb < 2; mb++) {
        const int row = m0 + wm*32 + mb*16 + g;
        #pragma unroll
        for (int nb = 0; nb < 8; nb++) {
            const int col = n0 + wn*64 + nb*8 + t4*2;
            const float bx = bias[col], by = bias[col+1];
            const float v0x = c[mb][nb][0] + bx, v0y = c[mb][nb][1] + by;
            const float v1x = c[mb][nb][2] + bx, v1y = c[mb][nb][3] + by;
            if (MODE == 0) {
                *(float2*)(outf + (size_t)row * DD + col)       = make_float2(v0x, v0y);
                *(float2*)(outf + (size_t)(row + 8) * DD + col) = make_float2(v1x, v1y);
            } else {
                const int h = col >> 6, d = col & 63;
                const int b0 = row >> 11, t0 = row & (TT-1);
                const int b1 = (row+8) >> 11, t1 = (row+8) & (TT-1);
                const size_t o0 = (((size_t)(b0*HH + h) * TT + t0) * HD) + d;
                const size_t o1 = (((size_t)(b1*HH + h) * TT + t1) * HD) + d;
                __nv_bfloat16 hx,hy,lx,ly;
                bsplit(v0x,hx,lx); bsplit(v0y,hy,ly);
                { __nv_bfloat162 p; p.x=hx; p.y=hy; *(__nv_bfloat162*)(outh+o0)=p;
                  p.x=lx; p.y=ly; *(__nv_bfloat162*)(outl+o0)=p; }
                bsplit(v1x,hx,lx); bsplit(v1y,hy,ly);
                { __nv_bfloat162 p; p.x=hx; p.y=hy; *(__nv_bfloat162*)(outh+o1)=p;
                  p.x=lx; p.y=ly; *(__nv_bfloat162*)(outl+o1)=p; }
            }
        }
    }
}

// ---------------------------------------------------------------------------
// Flash attention on mma.sync: causal + ALiBi, online softmax in registers.
// 64-query tile per CTA, 4 warps x 16 rows. Split-bf16 3-term S and PV.
// SMEM: Qhi/Qlo tiles + 2-stage double-buffered Khi/Klo/Vhi/Vlo tiles.
// 128B rows, SW128 swizzle (chunk ^= row&7). V b-frags via ldmatrix.trans.
// ---------------------------------------------------------------------------
#define A_QH 0
#define A_QL 8192
#define A_ST(s) (16384 + (s)*32768)
#define ATT_SMEM 81920

#define KV_PREFETCH(KT, STG) { \
    _Pragma("unroll") \
    for (int q_ = 0; q_ < 16; q_++) { \
        int idx_ = q_ * 128 + tid; \
        int arr_ = idx_ >> 9, wi2_ = idx_ & 511; \
        int row_ = wi2_ >> 3, ch_ = wi2_ & 7; \
        uint32_t dst_ = sb + A_ST(STG) + arr_*8192 + row_*128 + ((ch_ ^ (row_ & 7)) << 4); \
        const __nv_bfloat16* p_ = (arr_ == 0) ? Kh : (arr_ == 1) ? Kl : (arr_ == 2) ? Vh : Vl; \
        cpa(dst_, p_ + bo + (size_t)((KT)*64 + row_)*HD + ch_*8); \
    } }

__global__ __launch_bounds__(128, 2)
void attn_mma(const __nv_bfloat16* __restrict__ Qh, const __nv_bfloat16* __restrict__ Ql,
              const __nv_bfloat16* __restrict__ Kh, const __nv_bfloat16* __restrict__ Kl,
              const __nv_bfloat16* __restrict__ Vh, const __nv_bfloat16* __restrict__ Vl,
              __nv_bfloat16* __restrict__ Oh, __nv_bfloat16* __restrict__ Ol)
{
    extern __shared__ __align__(1024) char smem[];
    const uint32_t sb = smem_u32(smem);
    const int tid  = threadIdx.x, lane = tid & 31, warp = tid >> 5;
    const int g    = lane >> 2, t4 = lane & 3;
    const int grp  = lane >> 3, wi = lane & 7;
    const int qt   = (int)gridDim.x - 1 - (int)blockIdx.x;
    const int bh   = blockIdx.y, b = bh >> 4, h = bh & 15;
    const size_t bo = (size_t)bh * TT * HD;

    // prefetch Q tile (hi+lo) + KV stage 0 (one cp.async group)
    #pragma unroll
    for (int q = 0; q < 8; q++) {
        int idx = q * 128 + tid;
        int arr = idx >> 9, w2 = idx & 511;
        int row = w2 >> 3, ch = w2 & 7;
        uint32_t dst = sb + arr*8192 + row*128 + ((ch ^ (row & 7)) << 4);
        const __nv_bfloat16* src = (arr ? Ql : Qh) + bo + (size_t)(qt*64 + row)*HD + ch*8;
        cpa(dst, src);
    }
    KV_PREFETCH(0, 0); commitg();

    const float LOG2E  = 1.4426950408889634f;
    const float scale2 = 0.125f * LOG2E;
    const float slope2 = exp2f(-0.5f * (float)(h + 1)) * LOG2E;

    float cO[8][4];
    #pragma unroll
    for (int nb = 0; nb < 8; nb++)
        #pragma unroll
        for (int j = 0; j < 4; j++) cO[nb][j] = 0.f;
    float mr0 = -1e30f, mr1 = -1e30f, lr0 = 0.f, lr1 = 0.f;
    uint32_t qfh[4][4], qfl[4][4];

    for (int kt = 0; kt <= qt; kt++) {
        if (kt < qt) { KV_PREFETCH(kt+1, (kt+1)&1); commitg(); waitg<1>(); }
        else         { waitg<0>(); }
        __syncthreads();
        const uint32_t stb = sb + A_ST(kt & 1);

        if (kt == 0) {
            #pragma unroll
            for (int s = 0; s < 4; s++) {
                const int row = warp*16 + (grp & 1)*8 + wi;
                const int cb  = s*32 + (grp >> 1)*16;
                const uint32_t off = row*128 + ((uint32_t)cb ^ (uint32_t)((row & 7) << 4));
                ldsm4(sb + A_QH + off, qfh[s]);
                ldsm4(sb + A_QL + off, qfl[s]);
            }
        }

        // ---- S = Q K^T (3-term split) ----
        float cS[8][4];
        #pragma unroll
        for (int nb = 0; nb < 8; nb++)
            #pragma unroll
            for (int j = 0; j < 4; j++) cS[nb][j] = 0.f;

        #pragma unroll
        for (int s = 0; s < 4; s++) {
            #pragma unroll
            for (int nbp = 0; nbp < 4; nbp++) {
                const int row = nbp*16 + (grp >> 1)*8 + wi;
                const int cb  = s*32 + (grp & 1)*16;
                const uint32_t off = row*128 + ((uint32_t)cb ^ (uint32_t)((row & 7) << 4));
                uint32_t kh4[4], kl4[4];
                ldsm4(stb + off, kh4);
                ldsm4(stb + 8192 + off, kl4);
                mma_bf16(cS[2*nbp],   qfh[s], kh4[0], kh4[1]);
                mma_bf16(cS[2*nbp],   qfl[s], kh4[0], kh4[1]);
                mma_bf16(cS[2*nbp],   qfh[s], kl4[0], kl4[1]);
                mma_bf16(cS[2*nbp+1], qfh[s], kh4[2], kh4[3]);
                mma_bf16(cS[2*nbp+1], qfl[s], kh4[2], kh4[3]);
                mma_bf16(cS[2*nbp+1], qfh[s], kl4[2], kl4[3]);
            }
        }

        // ---- scale + ALiBi + causal + online softmax (log2 domain) ----
        const int r0 = qt*64 + warp*16 + g, r1 = r0 + 8;
        const bool diag = (kt == qt);
        float mx0 = -1e30f, mx1 = -1e30f;
        #pragma unroll
        for (int nb = 0; nb < 8; nb++) {
            const int k0i = kt*64 + nb*8 + t4*2;
            const float b0f = -slope2 * (float)(TT - 1 - k0i);
            const float b1f = -slope2 * (float)(TT - 2 - k0i);
            float v0 = fmaf(cS[nb][0], scale2, b0f);
            float v1 = fmaf(cS[nb][1], scale2, b1f);
            float v2 = fmaf(cS[nb][2], scale2, b0f);
            float v3 = fmaf(cS[nb][3], scale2, b1f);
            if (diag) {
                if (k0i     > r0) v0 = -1e30f;
                if (k0i + 1 > r0) v1 = -1e30f;
                if (k0i     > r1) v2 = -1e30f;
                if (k0i + 1 > r1) v3 = -1e30f;
            }
            cS[nb][0] = v0; cS[nb][1] = v1; cS[nb][2] = v2; cS[nb][3] = v3;
            mx0 = fmaxf(mx0, fmaxf(v0, v1));
            mx1 = fmaxf(mx1, fmaxf(v2, v3));
        }
        mx0 = fmaxf(mx0, __shfl_xor_sync(0xffffffffu, mx0, 1));
        mx0 = fmaxf(mx0, __shfl_xor_sync(0xffffffffu, mx0, 2));
        mx1 = fmaxf(mx1, __shfl_xor_sync(0xffffffffu, mx1, 1));
        mx1 = fmaxf(mx1, __shfl_xor_sync(0xffffffffu, mx1, 2));
        const float mn0 = fmaxf(mr0, mx0), mn1 = fmaxf(mr1, mx1);
        const float co0 = fast_exp2(mr0 - mn0), co1 = fast_exp2(mr1 - mn1);
        mr0 = mn0; mr1 = mn1;
        float s0 = 0.f, s1 = 0.f;
        #pragma unroll
        for (int nb = 0; nb < 8; nb++) {
            cS[nb][0] = fast_exp2(cS[nb][0] - mn0);
            cS[nb][1] = fast_exp2(cS[nb][1] - mn0);
            cS[nb][2] = fast_exp2(cS[nb][2] - mn1);
            cS[nb][3] = fast_exp2(cS[nb][3] - mn1);
            s0 += cS[nb][0] + cS[nb][1];
            s1 += cS[nb][2] + cS[nb][3];
        }
        s0 += __shfl_xor_sync(0xffffffffu, s0, 1);
        s0 += __shfl_xor_sync(0xffffffffu, s0, 2);
        s1 += __shfl_xor_sync(0xffffffffu, s1, 1);
        s1 += __shfl_xor_sync(0xffffffffu, s1, 2);
        lr0 = lr0 * co0 + s0;
        lr1 = lr1 * co1 + s1;
        #pragma unroll
        for (int nb = 0; nb < 8; nb++) {
            cO[nb][0] *= co0; cO[nb][1] *= co0;
            cO[nb][2] *= co1; cO[nb][3] *= co1;
        }

        // ---- pack P into split bf16 a-frags (in-register c->a reuse) ----
        uint32_t aPh[4][4], aPl[4][4];
        #pragma unroll
        for (int s = 0; s < 4; s++) {
            packsplit(cS[2*s][0],   cS[2*s][1],   aPh[s][0], aPl[s][0]);
            packsplit(cS[2*s][2],   cS[2*s][3],   aPh[s][1], aPl[s][1]);
            packsplit(cS[2*s+1][0], cS[2*s+1][1], aPh[s][2], aPl[s][2]);
            packsplit(cS[2*s+1][2], cS[2*s+1][3], aPh[s][3], aPl[s][3]);
        }

        // ---- O += P V (3-term split, V b-frags via ldmatrix.trans) ----
        #pragma unroll
        for (int s = 0; s < 4; s++) {
            #pragma unroll
            for (int nbp = 0; nbp < 4; nbp++) {
                const int row = s*16 + (grp & 1)*8 + wi;   // key rows
                const int cb  = nbp*32 + (grp >> 1)*16;     // d bytes
                const uint32_t off = row*128 + ((uint32_t)cb ^ (uint32_t)((row & 7) << 4));
                uint32_t vh4[4], vl4[4];
                ldsm4t(stb + 16384 + off, vh4);
                ldsm4t(stb + 24576 + off, vl4);
                mma_bf16(cO[2*nbp],   aPh[s], vh4[0], vh4[1]);
                mma_bf16(cO[2*nbp],   aPl[s], vh4[0], vh4[1]);
                mma_bf16(cO[2*nbp],   aPh[s], vl4[0], vl4[1]);
                mma_bf16(cO[2*nbp+1], aPh[s], vh4[2], vh4[3]);
                mma_bf16(cO[2*nbp+1], aPl[s], vh4[2], vh4[3]);
                mma_bf16(cO[2*nbp+1], aPh[s], vl4[2], vl4[3]);
            }
        }
        __syncthreads();
    }

    // ---- normalize + write split bf16 to (B,T,D) with head interleave ----
    const float i0 = 1.f / lr0, i1 = 1.f / lr1;
    const int t0 = qt*64 + warp*16 + g;
    #pragma unroll
    for (int nb = 0; nb < 8; nb++) {
        const int d = h*HD + nb*8 + t4*2;
        const size_t o0 = (size_t)(b*TT + t0) * DD + d;
        const size_t o1 = o0 + (size_t)8 * DD;
        __nv_bfloat16 hx,hy,lx,ly;
        bsplit(cO[nb][0]*i0, hx, lx); bsplit(cO[nb][1]*i0, hy, ly);
        { __nv_bfloat162 p; p.x=hx; p.y=hy; *(__nv_bfloat162*)(Oh+o0)=p;
          p.x=lx; p.y=ly; *(__nv_bfloat162*)(Ol+o0)=p; }
        bsplit(cO[nb][2]*i1, hx, lx); bsplit(cO[nb][3]*i1, hy, ly);
        { __nv_bfloat162 p; p.x=hx; p.y=hy; *(__nv_bfloat162*)(Oh+o1)=p;
          p.x=lx; p.y=ly; *(__nv_bfloat162*)(Ol+o1)=p; }
    }
}

// ---------------------------------------------------------------------------
extern "C" void kernel_launch(void* const* d_in, const int* in_sizes, int n_in,
                              void* d_out, int out_size)
{
    const float* x  = (const float*)d_in[0];
    const float* Wq = (const float*)d_in[1];
    const float* bq = (const float*)d_in[2];
    const float* Wk = (const float*)d_in[3];
    const float* bk = (const float*)d_in[4];
    const float* Wv = (const float*)d_in[5];
    const float* bv = (const float*)d_in[6];
    const float* Wo = (const float*)d_in[7];
    const float* bo = (const float*)d_in[8];
    float* out = (float*)d_out;

    __nv_bfloat16 *xhi,*xlo,*qhi,*qlo,*khi,*klo,*vhi,*vlo,*ahi,*alo,*whi,*wlo;
    cudaGetSymbolAddress((void**)&xhi, g_xhi);
    cudaGetSymbolAddress((void**)&xlo, g_xlo);
    cudaGetSymbolAddress((void**)&qhi, g_qhi);
    cudaGetSymbolAddress((void**)&qlo, g_qlo);
    cudaGetSymbolAddress((void**)&khi, g_khi);
    cudaGetSymbolAddress((void**)&klo, g_klo);
    cudaGetSymbolAddress((void**)&vhi, g_vhi);
    cudaGetSymbolAddress((void**)&vlo, g_vlo);
    cudaGetSymbolAddress((void**)&ahi, g_ahi);
    cudaGetSymbolAddress((void**)&alo, g_alo);
    cudaGetSymbolAddress((void**)&whi, g_whi);
    cudaGetSymbolAddress((void**)&wlo, g_wlo);

    cudaFuncSetAttribute(mma_gemm<0>, cudaFuncAttributeMaxDynamicSharedMemorySize, GEMM_SMEM);
    cudaFuncSetAttribute(mma_gemm<1>, cudaFuncAttributeMaxDynamicSharedMemorySize, GEMM_SMEM);
    cudaFuncSetAttribute(attn_mma,   cudaFuncAttributeMaxDynamicSharedMemorySize, ATT_SMEM);

    const size_t WSZ = (size_t)DD * DD;

    splitf<<<(MM*DD/4)/256, 256>>>(x, xhi, xlo);
    dim3 tg(32, 32), tb(32, 8);
    transp_split<<<tg, tb>>>(Wq, whi + 0*WSZ, wlo + 0*WSZ);
    transp_split<<<tg, tb>>>(Wk, whi + 1*WSZ, wlo + 1*WSZ);
    transp_split<<<tg, tb>>>(Wv, whi + 2*WSZ, wlo + 2*WSZ);
    transp_split<<<tg, tb>>>(Wo, whi + 3*WSZ, wlo + 3*WSZ);

    dim3 gg(DD/128, MM/128);   // (8, 32)
    mma_gemm<1><<<gg, 256, GEMM_SMEM>>>(xhi, xlo, whi + 0*WSZ, wlo + 0*WSZ, bq, nullptr, qhi, qlo);
    mma_gemm<1><<<gg, 256, GEMM_SMEM>>>(xhi, xlo, whi + 1*WSZ, wlo + 1*WSZ, bk, nullptr, khi, klo);
    mma_gemm<1><<<gg, 256, GEMM_SMEM>>>(xhi, xlo, whi + 2*WSZ, wlo + 2*WSZ, bv, nullptr, vhi, vlo);
    attn_mma<<<dim3(TT/64, BB*HH), 128, ATT_SMEM>>>(qhi, qlo, khi, klo, vhi, vlo, ahi, alo);
    mma_gemm<0><<<gg, 256, GEMM_SMEM>>>(ahi, alo, whi + 3*WSZ, wlo + 3*WSZ, bo, out, nullptr, nullptr);
}